// round 4
// baseline (speedup 1.0000x reference)
#include <cuda_runtime.h>
#include <math.h>

#define Nn   4
#define MA   256
#define NFS  128
#define KK   8
#define HID  256
#define OUTD 32
#define RCf  5.0f
#define PIf  3.14159265358979323846f
#define ROWS (Nn*MA)   // 1024

// ---------------- scratch ---------------------------------------------------
__device__ float g_a[ROWS];
__device__ float g_b[ROWS];
__device__ float g_p[ROWS*HID];
__device__ float g_q[ROWS*HID];

// ---------------- kernel A: per-atom projections (+ output prefix) ---------
// grid = 256 blocks: blockIdx = rowblk*2 + colhalf. 8 rows, 128 output cols.
__global__ void __launch_bounds__(256) kA(
        const float* __restrict__ h,
        const float* __restrict__ Wp1,
        const float* __restrict__ Wa,
        const int*   __restrict__ z,
        const float* __restrict__ r,
        float* __restrict__ out, int has_prefix) {
    __shared__ float hs[8*NFS];
    const int t    = threadIdx.x;
    const int row0 = (blockIdx.x >> 1) * 8;
    const int half = blockIdx.x & 1;
    for (int i = t; i < 8*NFS; i += 256) hs[i] = h[(size_t)row0*NFS + i];

    if (has_prefix) {
        const int gt = blockIdx.x * 256 + t;
        if (gt < ROWS)   out[gt] = (float)z[gt];
        if (gt < ROWS*3) out[ROWS + gt] = r[gt];
    }
    __syncthreads();

    const int col = half*128 + (t & 127);   // output column
    const int rg  = t >> 7;                 // 0/1 -> rows rg*4..rg*4+3

    float accp[4] = {0.f,0.f,0.f,0.f};
    float accq[4] = {0.f,0.f,0.f,0.f};

#pragma unroll 8
    for (int f = 0; f < NFS; f++) {
        const float wt = Wp1[(size_t)f*HID + col];
        const float wb = Wp1[(size_t)(NFS+f)*HID + col];
#pragma unroll
        for (int rr = 0; rr < 4; rr++) {
            const float hv = hs[(rg*4+rr)*NFS + f];
            accp[rr] = fmaf(hv, wt, accp[rr]);
            accq[rr] = fmaf(hv, wb, accq[rr]);
        }
    }
#pragma unroll
    for (int rr = 0; rr < 4; rr++) {
        g_p[(size_t)(row0 + rg*4 + rr)*HID + col] = accp[rr];
        g_q[(size_t)(row0 + rg*4 + rr)*HID + col] = accq[rr];
    }

    // a,b dots: only half==0 blocks; warps 0..7 handle rows 0..7
    if (half == 0) {
        const int w = t >> 5, lane = t & 31;
        float sa = 0.f, sb_ = 0.f;
        for (int f = lane; f < NFS; f += 32) {
            const float hv = hs[w*NFS + f];
            sa  = fmaf(hv, Wa[f],     sa);
            sb_ = fmaf(hv, Wa[NFS+f], sb_);
        }
#pragma unroll
        for (int off = 16; off; off >>= 1) {
            sa  += __shfl_down_sync(0xffffffffu, sa,  off);
            sb_ += __shfl_down_sync(0xffffffffu, sb_, off);
        }
        if (lane == 0) { g_a[row0+w] = sa; g_b[row0+w] = sb_; }
    }
}

// ---------------- kernel F: fused attention + topK + MLP + output ----------
// grid = 1024 (one block per row), 256 threads.
__global__ void __launch_bounds__(256) kF(
        const int*   __restrict__ z,
        const float* __restrict__ r,
        const float* __restrict__ ba_,
        const float* __restrict__ bp1,
        const float* __restrict__ Wp2,
        const float* __restrict__ bp2,
        float*       __restrict__ cout) {
    __shared__ float px[MA], py[MA], pz[MA], sbv[MA];
    __shared__ unsigned char smk[MA];
    __shared__ unsigned long long scand[64];
    __shared__ float wsum[8];
    __shared__ float satt[KK];
    __shared__ int   sidx[KK];
    __shared__ float sdx[KK], sdy[KK], sdz[KK];
    __shared__ float hid[KK][HID];
    __shared__ float sp[8*256];            // per-warp matvec partials

    const int t   = threadIdx.x;
    const int row = blockIdx.x;
    const int n   = row >> 8;
    const int i   = row & (MA-1);
    const int bse = n * MA;
    const int j   = t;

    px[j]  = r[(size_t)(bse+j)*3 + 0];
    py[j]  = r[(size_t)(bse+j)*3 + 1];
    pz[j]  = r[(size_t)(bse+j)*3 + 2];
    smk[j] = (z[bse+j] > -1) ? 1 : 0;
    sbv[j] = g_b[bse+j];
    const float b1  = bp1[t];
    const float bav = ba_[0];
    const float av  = g_a[row];
    __syncthreads();

    // ---- attention score ----
    const float dx = px[j]-px[i], dy = py[j]-py[i], dz = pz[j]-pz[i];
    const float d  = sqrtf(dx*dx + dy*dy + dz*dz);
    const bool  msk = smk[i] && smk[j] && (j != i);
    float g = 0.f;
    if (msk) {
        const float cf = 0.5f * (cosf(PIf * fminf(d, RCf) / RCf) + 1.f);
        g = expf(av + cf*sbv[j] + bav);
    }

    // ---- warp sums of g ----
    float s = g;
#pragma unroll
    for (int off = 16; off; off >>= 1) s += __shfl_xor_sync(0xffffffffu, s, off);
    if ((t & 31) == 0) wsum[t >> 5] = s;

    // ---- intra-warp exact full rank on unique u64 keys ----
    const unsigned long long key =
        (((unsigned long long)__float_as_uint(g)) << 32) | (unsigned)(MA-1-j);
    int rk = 0;
#pragma unroll
    for (int sft = 1; sft < 32; sft++) {
        const unsigned long long ok = __shfl_xor_sync(0xffffffffu, key, sft);
        rk += (ok > key);
    }
    if (rk < KK) scand[(t >> 5)*KK + rk] = key;
    __syncthreads();

    float sumg = 0.f;
#pragma unroll
    for (int w = 0; w < 8; w++) sumg += wsum[w];
    const float invsum = 1.f / fmaxf(sumg, 1e-8f);

    // ---- warp 0: rank the 64 candidates, emit global top-8 ----
    if (t < 32) {
        const unsigned long long k0 = scand[t], k1 = scand[t + 32];
        int r0 = 0, r1 = 0;
#pragma unroll 8
        for (int m = 0; m < 64; m++) {
            const unsigned long long km = scand[m];
            r0 += (km > k0);
            r1 += (km > k1);
        }
#pragma unroll
        for (int pick = 0; pick < 2; pick++) {
            const unsigned long long kk = pick ? k1 : k0;
            const int rr = pick ? r1 : r0;
            if (rr < KK) {
                const int jw = MA - 1 - (int)(kk & 0xffffffffu);
                satt[rr] = __uint_as_float((unsigned)(kk >> 32)) * invsum;
                sidx[rr] = jw;
                const float ddx = px[jw]-px[i], ddy = py[jw]-py[i], ddz = pz[jw]-pz[i];
                const float dd  = sqrtf(ddx*ddx + ddy*ddy + ddz*ddz);
                const float inv = 1.f / fmaxf(dd, 1e-4f);
                sdx[rr] = ddx*inv; sdy[rr] = ddy*inv; sdz[rr] = ddz*inv;
            }
        }
    }
    __syncthreads();

    // ---- MLP layer 1 ----
    const float pv = g_p[(size_t)row*HID + t];
#pragma unroll
    for (int k = 0; k < KK; k++) {
        const float x = fmaf(satt[k], pv + g_q[(size_t)(bse + sidx[k])*HID + t], b1);
        hid[k][t] = x / (1.f + expf(-x));   // silu
    }
    __syncthreads();

    // ---- layer 2 matvec: thread = (tt-group of 8, o-quad); each weight
    //      float4 is reused for 4 k's in registers (two k-passes) ----
    {
        const int tg   = t >> 3;          // 0..31 : tt in [tg*8, tg*8+8)
        const int oq   = t & 7;           // 0..7  : outputs oq*4..+3
        const int lane = t & 31;
        const int w    = t >> 5;

#pragma unroll
        for (int hk = 0; hk < 2; hk++) {  // k half: 0..3, 4..7
            float acc[4][4];
#pragma unroll
            for (int a = 0; a < 4; a++) { acc[a][0]=0.f; acc[a][1]=0.f; acc[a][2]=0.f; acc[a][3]=0.f; }
#pragma unroll
            for (int u = 0; u < 8; u++) {
                const int tt = tg*8 + u;
                const float4 wv = __ldg((const float4*)&Wp2[(size_t)tt*OUTD + oq*4]);
#pragma unroll
                for (int kk = 0; kk < 4; kk++) {
                    const float hv = hid[hk*4 + kk][tt];
                    acc[kk][0] = fmaf(hv, wv.x, acc[kk][0]);
                    acc[kk][1] = fmaf(hv, wv.y, acc[kk][1]);
                    acc[kk][2] = fmaf(hv, wv.z, acc[kk][2]);
                    acc[kk][3] = fmaf(hv, wv.w, acc[kk][3]);
                }
            }
            // reduce across the 4 tt-groups within this warp (lanes stride 8)
#pragma unroll
            for (int kk = 0; kk < 4; kk++) {
#pragma unroll
                for (int c = 0; c < 4; c++) {
                    float v = acc[kk][c];
                    v += __shfl_down_sync(0xffffffffu, v, 8);
                    v += __shfl_down_sync(0xffffffffu, v, 16);
                    if (lane < 8)
                        sp[w*256 + (hk*4+kk)*32 + oq*4 + c] = v;
                }
            }
        }
    }
    __syncthreads();

    // ---- finalize: combine 8 warp partials, bias + direction, store ----
    {
        const int k = t >> 5;            // sp index t = k*32 + o
        const int o = t & 31;
        float acc = bp2[o];
#pragma unroll
        for (int w2 = 0; w2 < 8; w2++) acc += sp[w2*256 + t];
        const size_t ob = ((size_t)(row*KK + k)*OUTD + o) * 3;
        cout[ob+0] = acc * sdx[k];
        cout[ob+1] = acc * sdy[k];
        cout[ob+2] = acc * sdz[k];
    }
}

// ---------------------------------------------------------------------------
extern "C" void kernel_launch(void* const* d_in, const int* in_sizes, int n_in,
                              void* d_out, int out_size) {
    const int*   z   = (const int*)  d_in[0];
    const float* r   = (const float*)d_in[1];
    const float* h   = (const float*)d_in[2];
    const float* Wa  = (const float*)d_in[3];
    const float* ba  = (const float*)d_in[4];
    const float* Wp1 = (const float*)d_in[5];
    const float* bp1 = (const float*)d_in[6];
    const float* Wp2 = (const float*)d_in[7];
    const float* bp2 = (const float*)d_in[8];

    float* out = (float*)d_out;
    const int CSZ  = Nn*MA*KK*OUTD*3;         // 786432
    const int PREF = ROWS + ROWS*3;           // 4096 (z + r)
    const int has_prefix = (out_size == CSZ + PREF) ? 1 : 0;
    float* cout = has_prefix ? (out + PREF) : out;

    kA<<<256,  256>>>(h, Wp1, Wa, z, r, out, has_prefix);
    kF<<<ROWS, 256>>>(z, r, ba, bp1, Wp2, bp2, cout);
}